// round 1
// baseline (speedup 1.0000x reference)
#include <cuda_runtime.h>
#include <math.h>

#define BATCH  2
#define SEQ    2048
#define DMODEL 1024
#define NHEAD  16
#define HDIM   64
#define D3     3072

// Static device scratch (allocation-free rule): Q/K/V in [B,H,S,hd] layout, vals in [B,S,D]
__device__ __align__(16) float g_Q[BATCH * NHEAD * SEQ * HDIM];
__device__ __align__(16) float g_K[BATCH * NHEAD * SEQ * HDIM];
__device__ __align__(16) float g_V[BATCH * NHEAD * SEQ * HDIM];
__device__ __align__(16) float g_vals[BATCH * SEQ * DMODEL];

// ---------------------------------------------------------------------------
// QKV GEMM: [4096,1024] @ [1024,3072] + bias, scatter epilogue to g_Q/g_K/g_V
// 128x128x16 tile, 256 threads, 8x8 per thread.
// ---------------------------------------------------------------------------
__global__ __launch_bounds__(256) void qkv_kernel(const float* __restrict__ X,
                                                  const float* __restrict__ W,
                                                  const float* __restrict__ bias) {
    __shared__ float As[16][128];   // k-major
    __shared__ float Bs[16][128];
    const int tid = threadIdx.x;
    const int tx = tid & 15, ty = tid >> 4;
    const int m0 = blockIdx.y * 128;
    const int n0 = blockIdx.x * 128;

    float acc[8][8];
#pragma unroll
    for (int i = 0; i < 8; i++)
#pragma unroll
        for (int j = 0; j < 8; j++) acc[i][j] = 0.f;

    for (int k0 = 0; k0 < DMODEL; k0 += 16) {
#pragma unroll
        for (int i = 0; i < 2; i++) {
            int f4 = tid + i * 256;
            int row = f4 >> 2;
            int kq = (f4 & 3) * 4;
            float4 v = *(const float4*)&X[(size_t)(m0 + row) * DMODEL + k0 + kq];
            As[kq + 0][row] = v.x; As[kq + 1][row] = v.y;
            As[kq + 2][row] = v.z; As[kq + 3][row] = v.w;
        }
#pragma unroll
        for (int i = 0; i < 2; i++) {
            int f4 = tid + i * 256;
            int row = f4 >> 5;
            int cq = (f4 & 31) * 4;
            *(float4*)&Bs[row][cq] = *(const float4*)&W[(size_t)(k0 + row) * D3 + n0 + cq];
        }
        __syncthreads();
#pragma unroll
        for (int kk = 0; kk < 16; kk++) {
            float a[8], b[8];
            *(float4*)&a[0] = *(float4*)&As[kk][8 * ty];
            *(float4*)&a[4] = *(float4*)&As[kk][8 * ty + 4];
            *(float4*)&b[0] = *(float4*)&Bs[kk][8 * tx];
            *(float4*)&b[4] = *(float4*)&Bs[kk][8 * tx + 4];
#pragma unroll
            for (int i = 0; i < 8; i++)
#pragma unroll
                for (int j = 0; j < 8; j++) acc[i][j] += a[i] * b[j];
        }
        __syncthreads();
    }

    // Epilogue: bias + scatter into Q/K/V scratch.
#pragma unroll
    for (int i = 0; i < 8; i++) {
        int m = m0 + 8 * ty + i;
        int bb = m >> 11;          // / SEQ
        int s  = m & (SEQ - 1);
#pragma unroll
        for (int j = 0; j < 8; j++) {
            int c = n0 + 8 * tx + j;
            float v = acc[i][j] + bias[c];
            int h = c / 192;
            int w = c - h * 192;
            size_t base = ((size_t)(bb * NHEAD + h) * SEQ + s) * HDIM;
            if (w < 64)       g_Q[base + w]       = v;
            else if (w < 128) g_K[base + w - 64]  = v;
            else              g_V[base + w - 128] = v;
        }
    }
}

// ---------------------------------------------------------------------------
// Flash-style attention: block = (64 queries, one (b,h)). Stream over 64-key
// tiles with online softmax. 256 threads as 16x16, 4x4 register tile.
// ---------------------------------------------------------------------------
#define ATTN_SMEM_FLOATS (4096 /*Qt*/ + 4096 /*Kt*/ + 4096 /*Vs*/ + 4096 /*Ms*/ + 64 * 65 /*Ps*/)
#define ATTN_SMEM_BYTES  (ATTN_SMEM_FLOATS * 4)

__global__ __launch_bounds__(256) void attn_kernel(const float* __restrict__ mask) {
    extern __shared__ float sm[];
    float* Qt = sm;              // [d][r], d-major, stride 64
    float* Kt = sm + 4096;       // [d][c]
    float* Vs = sm + 8192;       // [j][dd]
    float* Ms = sm + 12288;      // [r][c]
    float* Ps = sm + 16384;      // [r][j], stride 65 (bank-conflict pad)

    const int tid = threadIdx.x;
    const int tx = tid & 15, ty = tid >> 4;
    const int b = blockIdx.z, h = blockIdx.y;
    const int q0 = blockIdx.x * 64;

    const float* Qg = g_Q + (size_t)(b * NHEAD + h) * SEQ * HDIM;
    const float* Kg = g_K + (size_t)(b * NHEAD + h) * SEQ * HDIM;
    const float* Vg = g_V + (size_t)(b * NHEAD + h) * SEQ * HDIM;
    const float* Mg = mask + (size_t)b * SEQ * SEQ;

    // Load Q tile transposed (d-major).
#pragma unroll
    for (int i = 0; i < 4; i++) {
        int f4 = tid + i * 256;
        int r = f4 >> 4;
        int dq = (f4 & 15) * 4;
        float4 v = *(const float4*)&Qg[(size_t)(q0 + r) * HDIM + dq];
        Qt[(dq + 0) * 64 + r] = v.x; Qt[(dq + 1) * 64 + r] = v.y;
        Qt[(dq + 2) * 64 + r] = v.z; Qt[(dq + 3) * 64 + r] = v.w;
    }

    float m_i[4], l_i[4], acc[4][4];
#pragma unroll
    for (int i = 0; i < 4; i++) {
        m_i[i] = -1e30f; l_i[i] = 0.f;
#pragma unroll
        for (int j = 0; j < 4; j++) acc[i][j] = 0.f;
    }

    for (int kt = 0; kt < SEQ; kt += 64) {
        // Load K (transposed), V (natural), mask tile.
#pragma unroll
        for (int i = 0; i < 4; i++) {
            int f4 = tid + i * 256;
            int r = f4 >> 4;
            int dq = (f4 & 15) * 4;
            float4 v = *(const float4*)&Kg[(size_t)(kt + r) * HDIM + dq];
            Kt[(dq + 0) * 64 + r] = v.x; Kt[(dq + 1) * 64 + r] = v.y;
            Kt[(dq + 2) * 64 + r] = v.z; Kt[(dq + 3) * 64 + r] = v.w;
            *(float4*)&Vs[r * 64 + dq] = *(const float4*)&Vg[(size_t)(kt + r) * HDIM + dq];
            *(float4*)&Ms[r * 64 + dq] = *(const float4*)&Mg[(size_t)(q0 + r) * SEQ + kt + dq];
        }
        __syncthreads();

        // S = Q K^T (64x64 tile, 4x4 per thread)
        float s[4][4];
#pragma unroll
        for (int i = 0; i < 4; i++)
#pragma unroll
            for (int j = 0; j < 4; j++) s[i][j] = 0.f;

#pragma unroll 8
        for (int d = 0; d < 64; d++) {
            float q4[4], k4[4];
            *(float4*)q4 = *(float4*)&Qt[d * 64 + 4 * ty];
            *(float4*)k4 = *(float4*)&Kt[d * 64 + 4 * tx];
#pragma unroll
            for (int i = 0; i < 4; i++)
#pragma unroll
                for (int j = 0; j < 4; j++) s[i][j] += q4[i] * k4[j];
        }

        // scale + mask + row max
        float mt[4];
#pragma unroll
        for (int i = 0; i < 4; i++) {
            mt[i] = -1e30f;
#pragma unroll
            for (int j = 0; j < 4; j++) {
                float v = s[i][j] * 0.125f + Ms[(4 * ty + i) * 64 + 4 * tx + j];
                s[i][j] = v;
                mt[i] = fmaxf(mt[i], v);
            }
        }
#pragma unroll
        for (int off = 8; off >= 1; off >>= 1)
#pragma unroll
            for (int i = 0; i < 4; i++)
                mt[i] = fmaxf(mt[i], __shfl_xor_sync(0xffffffffu, mt[i], off));

        float rs[4], corr[4];
#pragma unroll
        for (int i = 0; i < 4; i++) {
            float mn = fmaxf(m_i[i], mt[i]);
            corr[i] = __expf(m_i[i] - mn);
            m_i[i] = mn;
            rs[i] = 0.f;
#pragma unroll
            for (int j = 0; j < 4; j++) {
                float p = __expf(s[i][j] - mn);
                s[i][j] = p;
                rs[i] += p;
            }
        }
#pragma unroll
        for (int off = 8; off >= 1; off >>= 1)
#pragma unroll
            for (int i = 0; i < 4; i++)
                rs[i] += __shfl_xor_sync(0xffffffffu, rs[i], off);

#pragma unroll
        for (int i = 0; i < 4; i++) {
            l_i[i] = l_i[i] * corr[i] + rs[i];
#pragma unroll
            for (int j = 0; j < 4; j++) acc[i][j] *= corr[i];
        }

        // Stage P for the P@V GEMM.
#pragma unroll
        for (int i = 0; i < 4; i++)
#pragma unroll
            for (int j = 0; j < 4; j++)
                Ps[(4 * ty + i) * 65 + 4 * tx + j] = s[i][j];
        __syncthreads();

        // O += P @ V
#pragma unroll 8
        for (int j = 0; j < 64; j++) {
            float v4[4];
            *(float4*)v4 = *(float4*)&Vs[j * 64 + 4 * tx];
            float p0 = Ps[(4 * ty + 0) * 65 + j];
            float p1 = Ps[(4 * ty + 1) * 65 + j];
            float p2 = Ps[(4 * ty + 2) * 65 + j];
            float p3 = Ps[(4 * ty + 3) * 65 + j];
#pragma unroll
            for (int jj = 0; jj < 4; jj++) {
                acc[0][jj] += p0 * v4[jj];
                acc[1][jj] += p1 * v4[jj];
                acc[2][jj] += p2 * v4[jj];
                acc[3][jj] += p3 * v4[jj];
            }
        }
        __syncthreads();
    }

    // Normalize and write to g_vals in [B,S,D] layout (D col = h*64 + dd).
#pragma unroll
    for (int i = 0; i < 4; i++) {
        float inv = 1.0f / l_i[i];
        size_t row = ((size_t)b * SEQ + q0 + 4 * ty + i) * DMODEL + h * HDIM + 4 * tx;
#pragma unroll
        for (int j = 0; j < 4; j++)
            g_vals[row + j] = acc[i][j] * inv;
    }
}

// ---------------------------------------------------------------------------
// Output projection: g_vals [4096,1024] @ Wo [1024,1024] + bo -> d_out
// ---------------------------------------------------------------------------
__global__ __launch_bounds__(256) void proj_kernel(const float* __restrict__ Wo,
                                                   const float* __restrict__ bo,
                                                   float* __restrict__ out) {
    __shared__ float As[16][128];
    __shared__ float Bs[16][128];
    const int tid = threadIdx.x;
    const int tx = tid & 15, ty = tid >> 4;
    const int m0 = blockIdx.y * 128;
    const int n0 = blockIdx.x * 128;

    float acc[8][8];
#pragma unroll
    for (int i = 0; i < 8; i++)
#pragma unroll
        for (int j = 0; j < 8; j++) acc[i][j] = 0.f;

    for (int k0 = 0; k0 < DMODEL; k0 += 16) {
#pragma unroll
        for (int i = 0; i < 2; i++) {
            int f4 = tid + i * 256;
            int row = f4 >> 2;
            int kq = (f4 & 3) * 4;
            float4 v = *(const float4*)&g_vals[(size_t)(m0 + row) * DMODEL + k0 + kq];
            As[kq + 0][row] = v.x; As[kq + 1][row] = v.y;
            As[kq + 2][row] = v.z; As[kq + 3][row] = v.w;
        }
#pragma unroll
        for (int i = 0; i < 2; i++) {
            int f4 = tid + i * 256;
            int row = f4 >> 5;
            int cq = (f4 & 31) * 4;
            *(float4*)&Bs[row][cq] = *(const float4*)&Wo[(size_t)(k0 + row) * DMODEL + n0 + cq];
        }
        __syncthreads();
#pragma unroll
        for (int kk = 0; kk < 16; kk++) {
            float a[8], b[8];
            *(float4*)&a[0] = *(float4*)&As[kk][8 * ty];
            *(float4*)&a[4] = *(float4*)&As[kk][8 * ty + 4];
            *(float4*)&b[0] = *(float4*)&Bs[kk][8 * tx];
            *(float4*)&b[4] = *(float4*)&Bs[kk][8 * tx + 4];
#pragma unroll
            for (int i = 0; i < 8; i++)
#pragma unroll
                for (int j = 0; j < 8; j++) acc[i][j] += a[i] * b[j];
        }
        __syncthreads();
    }

#pragma unroll
    for (int i = 0; i < 8; i++) {
        int m = m0 + 8 * ty + i;
#pragma unroll
        for (int j = 0; j < 8; j++) {
            int c = n0 + 8 * tx + j;
            out[(size_t)m * DMODEL + c] = acc[i][j] + bo[c];
        }
    }
}

// ---------------------------------------------------------------------------
extern "C" void kernel_launch(void* const* d_in, const int* in_sizes, int n_in,
                              void* d_out, int out_size) {
    const float* x    = (const float*)d_in[0];
    const float* mask = (const float*)d_in[1];
    const float* Wqkv = (const float*)d_in[2];
    const float* bqkv = (const float*)d_in[3];
    const float* Wo   = (const float*)d_in[4];
    const float* bo   = (const float*)d_in[5];
    float* out = (float*)d_out;

    cudaFuncSetAttribute(attn_kernel, cudaFuncAttributeMaxDynamicSharedMemorySize,
                         ATTN_SMEM_BYTES);

    dim3 gq(D3 / 128, (BATCH * SEQ) / 128);
    qkv_kernel<<<gq, 256>>>(x, Wqkv, bqkv);

    dim3 ga(SEQ / 64, NHEAD, BATCH);
    attn_kernel<<<ga, 256, ATTN_SMEM_BYTES>>>(mask);

    dim3 gp(DMODEL / 128, (BATCH * SEQ) / 128);
    proj_kernel<<<gp, 256>>>(Wo, bo, out);
}

// round 2
// speedup vs baseline: 1.4141x; 1.4141x over previous
#include <cuda_runtime.h>
#include <stdint.h>
#include <math.h>

#define BATCH  2
#define SEQ    2048
#define DMODEL 1024
#define NHEAD  16
#define HDIM   64
#define D3     3072

// Scratch (allocation-free rule). K stored TRANSPOSED: [B,H,HDIM,SEQ].
__device__ __align__(16) float g_Q   [BATCH * NHEAD * SEQ * HDIM];
__device__ __align__(16) float g_Kt  [BATCH * NHEAD * HDIM * SEQ];
__device__ __align__(16) float g_V   [BATCH * NHEAD * SEQ * HDIM];
__device__ __align__(16) float g_vals[BATCH * SEQ * DMODEL];

// ---- tf32 helpers -----------------------------------------------------------
__device__ __forceinline__ uint32_t f2tf(float x) {
    uint32_t u; asm("cvt.rna.tf32.f32 %0, %1;" : "=r"(u) : "f"(x)); return u;
}
__device__ __forceinline__ void split_tf32(float x, uint32_t& hi, uint32_t& lo) {
    hi = f2tf(x);
    lo = f2tf(x - __uint_as_float(hi));
}
__device__ __forceinline__ void mma8(float* c, const uint32_t* a, const uint32_t* b) {
    asm volatile(
        "mma.sync.aligned.m16n8k8.row.col.f32.tf32.tf32.f32 "
        "{%0,%1,%2,%3},{%4,%5,%6,%7},{%8,%9},{%0,%1,%2,%3};"
        : "+f"(c[0]), "+f"(c[1]), "+f"(c[2]), "+f"(c[3])
        : "r"(a[0]), "r"(a[1]), "r"(a[2]), "r"(a[3]), "r"(b[0]), "r"(b[1]));
}

// ---------------------------------------------------------------------------
// QKV GEMM: X[4096,1024] @ Wqkv[1024,3072] + bias; 3xTF32 mma.
// Block 128x128, BK=16, 8 warps (4M x 2N), warp tile 32x64.
// Epilogue scatters into g_Q / g_Kt(transposed) / g_V.
// ---------------------------------------------------------------------------
__global__ __launch_bounds__(256, 2) void qkv_kernel(const float* __restrict__ X,
                                                     const float* __restrict__ W,
                                                     const float* __restrict__ bias) {
    __shared__ float As[128 * 20];   // row-major [m][k], stride 20 (conflict-free frags)
    __shared__ float Bs[16 * 136];   // row-major [k][n], stride 136
    const int tid = threadIdx.x;
    const int lane = tid & 31, warp = tid >> 5;
    const int g = lane >> 2, t = lane & 3;
    const int wm = (warp & 3) * 32, wn = (warp >> 2) * 64;
    const int m0 = blockIdx.y * 128, n0 = blockIdx.x * 128;

    float c[2][8][4];
#pragma unroll
    for (int mi = 0; mi < 2; mi++)
#pragma unroll
        for (int jj = 0; jj < 8; jj++)
#pragma unroll
            for (int e = 0; e < 4; e++) c[mi][jj][e] = 0.f;

    for (int k0 = 0; k0 < DMODEL; k0 += 16) {
#pragma unroll
        for (int i = 0; i < 2; i++) {
            int f = tid + i * 256;
            int m = f >> 2, q = f & 3;
            *(float4*)&As[m * 20 + 4 * q] =
                *(const float4*)&X[(size_t)(m0 + m) * DMODEL + k0 + 4 * q];
        }
#pragma unroll
        for (int i = 0; i < 2; i++) {
            int f = tid + i * 256;
            int r = f >> 5, c4 = (f & 31) * 4;
            *(float4*)&Bs[r * 136 + c4] =
                *(const float4*)&W[(size_t)(k0 + r) * D3 + n0 + c4];
        }
        __syncthreads();

#pragma unroll
        for (int kk = 0; kk < 16; kk += 8) {
            uint32_t ah[2][4], al[2][4];
#pragma unroll
            for (int mi = 0; mi < 2; mi++) {
                int r0 = wm + mi * 16 + g;
                split_tf32(As[r0 * 20 + kk + t],           ah[mi][0], al[mi][0]);
                split_tf32(As[(r0 + 8) * 20 + kk + t],     ah[mi][1], al[mi][1]);
                split_tf32(As[r0 * 20 + kk + t + 4],       ah[mi][2], al[mi][2]);
                split_tf32(As[(r0 + 8) * 20 + kk + t + 4], ah[mi][3], al[mi][3]);
            }
#pragma unroll
            for (int jj = 0; jj < 8; jj++) {
                uint32_t bh[2], bl[2];
                int nn = wn + jj * 8 + g;
                split_tf32(Bs[(kk + t) * 136 + nn],     bh[0], bl[0]);
                split_tf32(Bs[(kk + t + 4) * 136 + nn], bh[1], bl[1]);
#pragma unroll
                for (int mi = 0; mi < 2; mi++) {
                    mma8(c[mi][jj], ah[mi], bh);
                    mma8(c[mi][jj], ah[mi], bl);
                    mma8(c[mi][jj], al[mi], bh);
                }
            }
        }
        __syncthreads();
    }

#pragma unroll
    for (int mi = 0; mi < 2; mi++)
#pragma unroll
        for (int jj = 0; jj < 8; jj++)
#pragma unroll
            for (int e = 0; e < 4; e++) {
                int row = m0 + wm + mi * 16 + g + ((e >= 2) ? 8 : 0);
                int col = n0 + wn + jj * 8 + 2 * t + (e & 1);
                float v = c[mi][jj][e] + bias[col];
                int bb = row >> 11;
                int s  = row & (SEQ - 1);
                int h  = col / 192;
                int w  = col - h * 192;
                if (w < 64)
                    g_Q[((size_t)(bb * NHEAD + h) * SEQ + s) * HDIM + w] = v;
                else if (w < 128)
                    g_Kt[((size_t)(bb * NHEAD + h) * HDIM + (w - 64)) * SEQ + s] = v;
                else
                    g_V[((size_t)(bb * NHEAD + h) * SEQ + s) * HDIM + (w - 128)] = v;
            }
}

// ---------------------------------------------------------------------------
// Flash attention, tensor-core 3xTF32. Block = 128 queries x one (b,h).
// 8 warps; warp w owns query rows [16w,16w+16). Key tiles of 64.
// ---------------------------------------------------------------------------
#define ATTN_SMEM_FLOATS (128 * 68 + 64 * 72 + 64 * 72 + 8 * 16 * 72)
#define ATTN_SMEM_BYTES  (ATTN_SMEM_FLOATS * 4)

__global__ __launch_bounds__(256) void attn_kernel(const float* __restrict__ mask) {
    extern __shared__ float sm[];
    float* Qs = sm;                       // [128][68] row-major
    float* Ks = Qs + 128 * 68;            // [d][key] stride 72
    float* Vs = Ks + 64 * 72;             // [key][d] stride 72
    float* Ps = Vs + 64 * 72;             // per-warp [16][72]

    const int tid = threadIdx.x, lane = tid & 31, w = tid >> 5;
    const int g = lane >> 2, t = lane & 3;
    const int b = blockIdx.z, h = blockIdx.y;
    const int q0 = blockIdx.x * 128;
    const int qrow = w * 16 + g;

    const float* Qg = g_Q  + (size_t)(b * NHEAD + h) * SEQ * HDIM;
    const float* Kg = g_Kt + (size_t)(b * NHEAD + h) * HDIM * SEQ;
    const float* Vg = g_V  + (size_t)(b * NHEAD + h) * SEQ * HDIM;
    const float* Mg = mask + (size_t)b * SEQ * SEQ;
    float* Pw = Ps + w * (16 * 72);

    // Load Q tile [128][64] row-major (coalesced, conflict-free STS.128)
#pragma unroll
    for (int i = 0; i < 8; i++) {
        int f = tid + i * 256;
        int m = f >> 4, q = f & 15;
        *(float4*)&Qs[m * 68 + 4 * q] =
            *(const float4*)&Qg[(size_t)(q0 + m) * HDIM + 4 * q];
    }

    float o[8][4];
#pragma unroll
    for (int jj = 0; jj < 8; jj++)
#pragma unroll
        for (int e = 0; e < 4; e++) o[jj][e] = 0.f;
    float m0r = -1e30f, m1r = -1e30f, l0 = 0.f, l1 = 0.f;

    for (int kt = 0; kt < SEQ; kt += 64) {
        __syncthreads();
        // K^T tile: rows d, cols keys (coalesced from g_Kt)
#pragma unroll
        for (int i = 0; i < 4; i++) {
            int f = tid + i * 256;
            int r = f >> 4, q = f & 15;
            *(float4*)&Ks[r * 72 + 4 * q] =
                *(const float4*)&Kg[(size_t)r * SEQ + kt + 4 * q];
        }
        // V tile: rows keys, cols d
#pragma unroll
        for (int i = 0; i < 4; i++) {
            int f = tid + i * 256;
            int r = f >> 4, q = f & 15;
            *(float4*)&Vs[r * 72 + 4 * q] =
                *(const float4*)&Vg[(size_t)(kt + r) * HDIM + 4 * q];
        }
        __syncthreads();

        // S = Q @ K^T  (warp: 16 x 64)
        float s[8][4];
#pragma unroll
        for (int jj = 0; jj < 8; jj++)
#pragma unroll
            for (int e = 0; e < 4; e++) s[jj][e] = 0.f;

#pragma unroll
        for (int kk = 0; kk < 64; kk += 8) {
            uint32_t ah[4], al[4];
            split_tf32(Qs[qrow * 68 + kk + t],           ah[0], al[0]);
            split_tf32(Qs[(qrow + 8) * 68 + kk + t],     ah[1], al[1]);
            split_tf32(Qs[qrow * 68 + kk + t + 4],       ah[2], al[2]);
            split_tf32(Qs[(qrow + 8) * 68 + kk + t + 4], ah[3], al[3]);
#pragma unroll
            for (int jj = 0; jj < 8; jj++) {
                uint32_t bh[2], bl[2];
                int nn = jj * 8 + g;
                split_tf32(Ks[(kk + t) * 72 + nn],     bh[0], bl[0]);
                split_tf32(Ks[(kk + t + 4) * 72 + nn], bh[1], bl[1]);
                mma8(s[jj], ah, bh);
                mma8(s[jj], ah, bl);
                mma8(s[jj], al, bh);
            }
        }

        // scale + additive mask + row max
        float vm0 = -1e30f, vm1 = -1e30f;
#pragma unroll
        for (int jj = 0; jj < 8; jj++) {
            int col = kt + jj * 8 + 2 * t;
            float2 mk0 = *(const float2*)&Mg[(size_t)(q0 + qrow) * SEQ + col];
            float2 mk1 = *(const float2*)&Mg[(size_t)(q0 + qrow + 8) * SEQ + col];
            s[jj][0] = s[jj][0] * 0.125f + mk0.x;
            s[jj][1] = s[jj][1] * 0.125f + mk0.y;
            s[jj][2] = s[jj][2] * 0.125f + mk1.x;
            s[jj][3] = s[jj][3] * 0.125f + mk1.y;
            vm0 = fmaxf(vm0, fmaxf(s[jj][0], s[jj][1]));
            vm1 = fmaxf(vm1, fmaxf(s[jj][2], s[jj][3]));
        }
        vm0 = fmaxf(vm0, __shfl_xor_sync(0xffffffffu, vm0, 1));
        vm0 = fmaxf(vm0, __shfl_xor_sync(0xffffffffu, vm0, 2));
        vm1 = fmaxf(vm1, __shfl_xor_sync(0xffffffffu, vm1, 1));
        vm1 = fmaxf(vm1, __shfl_xor_sync(0xffffffffu, vm1, 2));

        float mn0 = fmaxf(m0r, vm0), mn1 = fmaxf(m1r, vm1);
        float cor0 = __expf(m0r - mn0), cor1 = __expf(m1r - mn1);
        m0r = mn0; m1r = mn1;
        float rs0 = 0.f, rs1 = 0.f;
#pragma unroll
        for (int jj = 0; jj < 8; jj++) {
            s[jj][0] = __expf(s[jj][0] - mn0);
            s[jj][1] = __expf(s[jj][1] - mn0);
            s[jj][2] = __expf(s[jj][2] - mn1);
            s[jj][3] = __expf(s[jj][3] - mn1);
            rs0 += s[jj][0] + s[jj][1];
            rs1 += s[jj][2] + s[jj][3];
        }
        rs0 += __shfl_xor_sync(0xffffffffu, rs0, 1);
        rs0 += __shfl_xor_sync(0xffffffffu, rs0, 2);
        rs1 += __shfl_xor_sync(0xffffffffu, rs1, 1);
        rs1 += __shfl_xor_sync(0xffffffffu, rs1, 2);
        l0 = l0 * cor0 + rs0;
        l1 = l1 * cor1 + rs1;
#pragma unroll
        for (int jj = 0; jj < 8; jj++) {
            o[jj][0] *= cor0; o[jj][1] *= cor0;
            o[jj][2] *= cor1; o[jj][3] *= cor1;
        }

        // Stage P (per-warp region; no block sync needed)
#pragma unroll
        for (int jj = 0; jj < 8; jj++) {
            *(float2*)&Pw[g * 72 + jj * 8 + 2 * t]       = make_float2(s[jj][0], s[jj][1]);
            *(float2*)&Pw[(g + 8) * 72 + jj * 8 + 2 * t] = make_float2(s[jj][2], s[jj][3]);
        }
        __syncwarp();

        // O += P @ V
#pragma unroll
        for (int kk = 0; kk < 64; kk += 8) {
            uint32_t ah[4], al[4];
            split_tf32(Pw[g * 72 + kk + t],           ah[0], al[0]);
            split_tf32(Pw[(g + 8) * 72 + kk + t],     ah[1], al[1]);
            split_tf32(Pw[g * 72 + kk + t + 4],       ah[2], al[2]);
            split_tf32(Pw[(g + 8) * 72 + kk + t + 4], ah[3], al[3]);
#pragma unroll
            for (int jj = 0; jj < 8; jj++) {
                uint32_t bh[2], bl[2];
                int nn = jj * 8 + g;
                split_tf32(Vs[(kk + t) * 72 + nn],     bh[0], bl[0]);
                split_tf32(Vs[(kk + t + 4) * 72 + nn], bh[1], bl[1]);
                mma8(o[jj], ah, bh);
                mma8(o[jj], ah, bl);
                mma8(o[jj], al, bh);
            }
        }
        __syncwarp();
    }

    // Normalize + write to g_vals [B,S,D]
    float inv0 = 1.f / l0, inv1 = 1.f / l1;
#pragma unroll
    for (int jj = 0; jj < 8; jj++) {
        size_t r0a = (size_t)(b * SEQ + q0 + qrow) * DMODEL + h * HDIM + jj * 8 + 2 * t;
        size_t r1a = (size_t)(b * SEQ + q0 + qrow + 8) * DMODEL + h * HDIM + jj * 8 + 2 * t;
        *(float2*)&g_vals[r0a] = make_float2(o[jj][0] * inv0, o[jj][1] * inv0);
        *(float2*)&g_vals[r1a] = make_float2(o[jj][2] * inv1, o[jj][3] * inv1);
    }
}

// ---------------------------------------------------------------------------
// Output projection: g_vals[4096,1024] @ Wo[1024,1024] + bo -> out. 3xTF32.
// ---------------------------------------------------------------------------
__global__ __launch_bounds__(256, 2) void proj_kernel(const float* __restrict__ Wo,
                                                      const float* __restrict__ bo,
                                                      float* __restrict__ out) {
    __shared__ float As[128 * 20];
    __shared__ float Bs[16 * 136];
    const int tid = threadIdx.x;
    const int lane = tid & 31, warp = tid >> 5;
    const int g = lane >> 2, t = lane & 3;
    const int wm = (warp & 3) * 32, wn = (warp >> 2) * 64;
    const int m0 = blockIdx.y * 128, n0 = blockIdx.x * 128;

    float c[2][8][4];
#pragma unroll
    for (int mi = 0; mi < 2; mi++)
#pragma unroll
        for (int jj = 0; jj < 8; jj++)
#pragma unroll
            for (int e = 0; e < 4; e++) c[mi][jj][e] = 0.f;

    for (int k0 = 0; k0 < DMODEL; k0 += 16) {
#pragma unroll
        for (int i = 0; i < 2; i++) {
            int f = tid + i * 256;
            int m = f >> 2, q = f & 3;
            *(float4*)&As[m * 20 + 4 * q] =
                *(const float4*)&g_vals[(size_t)(m0 + m) * DMODEL + k0 + 4 * q];
        }
#pragma unroll
        for (int i = 0; i < 2; i++) {
            int f = tid + i * 256;
            int r = f >> 5, c4 = (f & 31) * 4;
            *(float4*)&Bs[r * 136 + c4] =
                *(const float4*)&Wo[(size_t)(k0 + r) * DMODEL + n0 + c4];
        }
        __syncthreads();

#pragma unroll
        for (int kk = 0; kk < 16; kk += 8) {
            uint32_t ah[2][4], al[2][4];
#pragma unroll
            for (int mi = 0; mi < 2; mi++) {
                int r0 = wm + mi * 16 + g;
                split_tf32(As[r0 * 20 + kk + t],           ah[mi][0], al[mi][0]);
                split_tf32(As[(r0 + 8) * 20 + kk + t],     ah[mi][1], al[mi][1]);
                split_tf32(As[r0 * 20 + kk + t + 4],       ah[mi][2], al[mi][2]);
                split_tf32(As[(r0 + 8) * 20 + kk + t + 4], ah[mi][3], al[mi][3]);
            }
#pragma unroll
            for (int jj = 0; jj < 8; jj++) {
                uint32_t bh[2], bl[2];
                int nn = wn + jj * 8 + g;
                split_tf32(Bs[(kk + t) * 136 + nn],     bh[0], bl[0]);
                split_tf32(Bs[(kk + t + 4) * 136 + nn], bh[1], bl[1]);
#pragma unroll
                for (int mi = 0; mi < 2; mi++) {
                    mma8(c[mi][jj], ah[mi], bh);
                    mma8(c[mi][jj], ah[mi], bl);
                    mma8(c[mi][jj], al[mi], bh);
                }
            }
        }
        __syncthreads();
    }

#pragma unroll
    for (int mi = 0; mi < 2; mi++)
#pragma unroll
        for (int jj = 0; jj < 8; jj++) {
            int row0 = m0 + wm + mi * 16 + g;
            int col  = n0 + wn + jj * 8 + 2 * t;
            float b0 = bo[col], b1 = bo[col + 1];
            *(float2*)&out[(size_t)row0 * DMODEL + col] =
                make_float2(c[mi][jj][0] + b0, c[mi][jj][1] + b1);
            *(float2*)&out[(size_t)(row0 + 8) * DMODEL + col] =
                make_float2(c[mi][jj][2] + b0, c[mi][jj][3] + b1);
        }
}

// ---------------------------------------------------------------------------
extern "C" void kernel_launch(void* const* d_in, const int* in_sizes, int n_in,
                              void* d_out, int out_size) {
    const float* x    = (const float*)d_in[0];
    const float* mask = (const float*)d_in[1];
    const float* Wqkv = (const float*)d_in[2];
    const float* bqkv = (const float*)d_in[3];
    const float* Wo   = (const float*)d_in[4];
    const float* bo   = (const float*)d_in[5];
    float* out = (float*)d_out;

    cudaFuncSetAttribute(attn_kernel, cudaFuncAttributeMaxDynamicSharedMemorySize,
                         ATTN_SMEM_BYTES);

    dim3 gq(D3 / 128, (BATCH * SEQ) / 128);
    qkv_kernel<<<gq, 256>>>(x, Wqkv, bqkv);

    dim3 ga(SEQ / 128, NHEAD, BATCH);
    attn_kernel<<<ga, 256, ATTN_SMEM_BYTES>>>(mask);

    dim3 gp(DMODEL / 128, (BATCH * SEQ) / 128);
    proj_kernel<<<gp, 256>>>(Wo, bo, out);
}